// round 15
// baseline (speedup 1.0000x reference)
#include <cuda_runtime.h>
#include <cuda_fp16.h>
#include <cstdint>

constexpr int B_  = 4;
constexpr int S_  = 2048;
constexpr int DM  = 1024;
constexpr int H_  = 16;
constexpr int DK_ = 64;
constexpr int DV_ = 64;
constexpr int ROWS = B_ * S_;
constexpr float SCALE2 = 11.54156003f;   // 8 * log2(e); folded into Q at proj time
constexpr float NEG    = -1000000000.0f;

constexpr int NSM      = 152;            // GB300 SM count
constexpr int PERSIST  = 2 * NSM;        // 2 CTAs/SM
constexpr int PROJ_NT  = 1536;           // 512 Q + 512 K + 512 V tile slots
constexpr int ATTN_NT  = 1024;

// Pre-split inputs (hi/lo fp16)
__device__ __half g_ah[3][(size_t)ROWS * DM];
__device__ __half g_al[2][(size_t)ROWS * DM];
__device__ __half g_wh[3][(size_t)DM * DM];
__device__ __half g_wl[2][(size_t)DM * DM];

// Head-major projected tensors (Q pre-scaled by SCALE2)
__device__ __half g_qh_hi[(size_t)B_*H_*S_*DK_];
__device__ __half g_qh_lo[(size_t)B_*H_*S_*DK_];

// Mask compaction + compacted K/V (written directly by proj)
__device__ int    g_idx[B_][S_];
__device__ int    g_cnt[B_];
__device__ __half g_kc[(size_t)B_*H_*S_*DK_];
__device__ __half g_vc[(size_t)B_*H_*S_*DV_];

// Persistent work counters (reset by prep each launch/replay)
__device__ unsigned int g_ctr0;
__device__ unsigned int g_ctr1;

// ---------------------------------------------------------------------------
// primitives
// ---------------------------------------------------------------------------
__device__ __forceinline__ uint32_t smaddr(const void* p) {
    return (uint32_t)__cvta_generic_to_shared(p);
}
__device__ __forceinline__ void ldsm_x4(uint32_t (&r)[4], uint32_t a) {
    asm volatile("ldmatrix.sync.aligned.m8n8.x4.shared.b16 {%0,%1,%2,%3}, [%4];"
                 : "=r"(r[0]), "=r"(r[1]), "=r"(r[2]), "=r"(r[3]) : "r"(a));
}
__device__ __forceinline__ void ldsm_x4_t(uint32_t (&r)[4], uint32_t a) {
    asm volatile("ldmatrix.sync.aligned.m8n8.x4.trans.shared.b16 {%0,%1,%2,%3}, [%4];"
                 : "=r"(r[0]), "=r"(r[1]), "=r"(r[2]), "=r"(r[3]) : "r"(a));
}
__device__ __forceinline__ void mma16816(float (&c)[4], const uint32_t (&a)[4],
                                         uint32_t b0, uint32_t b1) {
    asm volatile(
        "mma.sync.aligned.m16n8k16.row.col.f32.f16.f16.f32 "
        "{%0,%1,%2,%3}, {%4,%5,%6,%7}, {%8,%9}, {%0,%1,%2,%3};"
        : "+f"(c[0]), "+f"(c[1]), "+f"(c[2]), "+f"(c[3])
        : "r"(a[0]), "r"(a[1]), "r"(a[2]), "r"(a[3]), "r"(b0), "r"(b1));
}
__device__ __forceinline__ uint32_t packh2(float x, float y) {
    __half2 h = __floats2half2_rn(x, y);
    return *reinterpret_cast<uint32_t*>(&h);
}
__device__ __forceinline__ float ex2f(float x) {
    float y; asm("ex2.approx.ftz.f32 %0, %1;" : "=f"(y) : "f"(x)); return y;
}
__device__ __forceinline__ uint32_t ex2h2(float a, float b) {
    uint32_t h = packh2(a, b);
    uint32_t r; asm("ex2.approx.f16x2 %0, %1;" : "=r"(r) : "r"(h)); return r;
}
#define CP16(dst, src) asm volatile("cp.async.cg.shared.global [%0], [%1], 16;\n" :: "r"(dst), "l"(src))
#define CPC()          asm volatile("cp.async.commit_group;\n")
#define CPW(n)         asm volatile("cp.async.wait_group %0;\n" :: "n"(n))

// ---------------------------------------------------------------------------
// Kernel 0: merged preprocessing — A splits, W splits, mask scan, counter reset
// ---------------------------------------------------------------------------
__device__ __forceinline__ void split_one(const float* __restrict__ src,
                                          __half* __restrict__ hi,
                                          __half* __restrict__ lo, size_t i)
{
    float4 vv = ((const float4*)src)[i];
    float f[4] = {vv.x, vv.y, vv.z, vv.w};
    __half h[4], l[4];
    #pragma unroll
    for (int e = 0; e < 4; e++) {
        h[e] = __float2half_rn(f[e]);
        l[e] = __float2half_rn(f[e] - __half2float(h[e]));
    }
    uint2 ph, pl;
    ph.x = (uint32_t)__half_as_ushort(h[0]) | ((uint32_t)__half_as_ushort(h[1]) << 16);
    ph.y = (uint32_t)__half_as_ushort(h[2]) | ((uint32_t)__half_as_ushort(h[3]) << 16);
    pl.x = (uint32_t)__half_as_ushort(l[0]) | ((uint32_t)__half_as_ushort(l[1]) << 16);
    pl.y = (uint32_t)__half_as_ushort(l[2]) | ((uint32_t)__half_as_ushort(l[3]) << 16);
    ((uint2*)hi)[i] = ph;
    if (lo) ((uint2*)lo)[i] = pl;
}

constexpr int PREP_A_BLKS = (ROWS * DM / 4) / 256;
constexpr int PREP_W_BLKS = (DM * DM / 4) / 256;

__global__ __launch_bounds__(256) void prep(
    const float* __restrict__ q,  const float* __restrict__ k,  const float* __restrict__ v,
    const float* __restrict__ wq, const float* __restrict__ wk, const float* __restrict__ wv,
    const int* __restrict__ mask)
{
    const int bid = blockIdx.x;
    const int tid = threadIdx.x;
    if (bid < 3 * PREP_A_BLKS) {
        int z = bid / PREP_A_BLKS;
        size_t i = (size_t)(bid % PREP_A_BLKS) * 256 + tid;
        const float* src = (z == 0) ? q : (z == 1) ? k : v;
        split_one(src, g_ah[z], (z < 2) ? g_al[z] : nullptr, i);
    } else if (bid < 3 * PREP_A_BLKS + 3 * PREP_W_BLKS) {
        int idx = bid - 3 * PREP_A_BLKS;
        int z = idx / PREP_W_BLKS;
        size_t i = (size_t)(idx % PREP_W_BLKS) * 256 + tid;
        const float* src = (z == 0) ? wq : (z == 1) ? wk : wv;
        split_one(src, g_wh[z], (z < 2) ? g_wl[z] : nullptr, i);
    } else {
        if (tid < 128) {
            const int bw   = tid >> 5;
            const int lane = tid & 31;
            const int* mrow = mask + (size_t)bw * S_;
            int running = 0;
            for (int s0 = 0; s0 < S_; s0 += 32) {
                int m = mrow[s0 + lane];
                unsigned bal = __ballot_sync(0xffffffffu, m != 0);
                int pre = __popc(bal & ((1u << lane) - 1u));
                if (m != 0) g_idx[bw][running + pre] = s0 + lane;
                running += __popc(bal);
            }
            if (lane == 0) g_cnt[bw] = running;
            for (int j = running + lane; j < S_; j += 32) g_idx[bw][j] = 0;
        } else if (tid == 128) {
            g_ctr0 = 0;
            g_ctr1 = 0;
        }
    }
}

// ---------------------------------------------------------------------------
// Kernel 1: PERSISTENT projection GEMM. 304 CTAs pull flattened tiles:
// t<512: Q (z=0), t<1024: K (z=1, compacted), else V (z=2, compacted).
// Tile body = R13 (double-buffered, chain-broken phases) — numerics identical.
// ---------------------------------------------------------------------------
struct ProjSmem {
    __half Ah[2][128][40];
    __half Al[2][128][40];
    __half Wh[2][32][136];
    __half Wl[2][32][136];
};                                            // 75,776 B
constexpr int PROJ_SMEM = sizeof(ProjSmem) + 16;

__global__ __launch_bounds__(256, 2) void proj_mma(
    const float* __restrict__ bq, const float* __restrict__ bk, const float* __restrict__ bv)
{
    extern __shared__ char smraw[];
    ProjSmem& S = *reinterpret_cast<ProjSmem*>(smraw);
    int* wslot = (int*)(smraw + sizeof(ProjSmem));

    const int tid  = threadIdx.x;
    const int lane = tid & 31;
    const int warp = tid >> 5;
    const int wr = warp >> 1, wc = warp & 1;

    for (;;) {
        if (tid == 0) *wslot = (int)atomicAdd(&g_ctr0, 1u);
        __syncthreads();
        const int t = *wslot;
        __syncthreads();
        if (t >= PROJ_NT) break;

        // decode tile
        int z, xx, yy;
        if (t < 512)       { z = 0; xx = t & 7;          yy = t >> 3; }
        else if (t < 1024) { z = 1; xx = (t - 512) & 7;  yy = (t - 512) >> 3; }
        else               { z = 2; xx = (t - 1024) & 7; yy = (t - 1024) >> 3; }

        int bb = 0, j0 = 0, m_blk = 0;
        if (z == 0) {
            m_blk = yy * 128;
        } else {
            bb = yy >> 4;
            j0 = (yy & 15) * 128;
            int npad = (g_cnt[bb] + 63) & ~63;
            if (j0 >= npad) continue;          // empty tile; wslot reread is sync-guarded
        }

        const __half* Agh = g_ah[z];
        const __half* Agl = (z < 2) ? g_al[z] : g_ah[z];
        const __half* Wgh = g_wh[z];
        const __half* Wgl = (z < 2) ? g_wl[z] : g_wh[z];
        const float* bias = (z == 0) ? bq : (z == 1) ? bk : bv;
        const int n_blk = xx * 128;

        const int ar = tid >> 1;
        size_t arow_off;
        if (z == 0) arow_off = (size_t)(m_blk + ar) * DM;
        else        arow_off = ((size_t)bb * S_ + g_idx[bb][j0 + ar]) * DM;

        float acc[2][8][4];
        #pragma unroll
        for (int mt = 0; mt < 2; mt++)
            #pragma unroll
            for (int nt = 0; nt < 8; nt++)
                #pragma unroll
                for (int e = 0; e < 4; e++) acc[mt][nt][e] = 0.0f;

        auto load_tile = [&](int kt, int buf) {
            const int k0 = kt * 32;
            #pragma unroll
            for (int i = 0; i < 2; i++) {
                int ac = ((tid & 1) * 2 + i) * 8;
                size_t aoff = arow_off + k0 + ac;
                CP16(smaddr(&S.Ah[buf][ar][ac]), Agh + aoff);
                if (z < 2) CP16(smaddr(&S.Al[buf][ar][ac]), Agl + aoff);
            }
            #pragma unroll
            for (int i = 0; i < 2; i++) {
                int idx = tid * 2 + i;
                int wrow = idx >> 4, wcol = (idx & 15) * 8;
                size_t woff = (size_t)(k0 + wrow) * DM + n_blk + wcol;
                CP16(smaddr(&S.Wh[buf][wrow][wcol]), Wgh + woff);
                if (z < 2) CP16(smaddr(&S.Wl[buf][wrow][wcol]), Wgl + woff);
            }
            CPC();
        };

        load_tile(0, 0);

        for (int kt = 0; kt < DM / 32; kt++) {
            const int buf = kt & 1;
            CPW(0);
            __syncthreads();
            if (kt + 1 < DM / 32) load_tile(kt + 1, buf ^ 1);

            #pragma unroll
            for (int kc = 0; kc < 2; kc++) {
                uint32_t afh[2][4], afl[2][4];
                #pragma unroll
                for (int mt = 0; mt < 2; mt++) {
                    int row = wr * 32 + mt * 16 + (lane & 15);
                    int col = kc * 16 + (lane >> 4) * 8;
                    ldsm_x4(afh[mt], smaddr(&S.Ah[buf][row][col]));
                    if (z < 2) ldsm_x4(afl[mt], smaddr(&S.Al[buf][row][col]));
                }
                #pragma unroll
                for (int ntp = 0; ntp < 4; ntp++) {
                    uint32_t bh[4], bl[4];
                    int krow = kc * 16 + (lane & 15);
                    int ncol = wc * 64 + ntp * 16 + (lane >> 4) * 8;
                    ldsm_x4_t(bh, smaddr(&S.Wh[buf][krow][ncol]));
                    if (z < 2) ldsm_x4_t(bl, smaddr(&S.Wl[buf][krow][ncol]));
                    // phase 1: hh
                    #pragma unroll
                    for (int mt = 0; mt < 2; mt++) {
                        mma16816(acc[mt][2*ntp],   afh[mt], bh[0], bh[1]);
                        mma16816(acc[mt][2*ntp+1], afh[mt], bh[2], bh[3]);
                    }
                    if (z < 2) {
                        // phase 2: hl
                        #pragma unroll
                        for (int mt = 0; mt < 2; mt++) {
                            mma16816(acc[mt][2*ntp],   afh[mt], bl[0], bl[1]);
                            mma16816(acc[mt][2*ntp+1], afh[mt], bl[2], bl[3]);
                        }
                        // phase 3: lh
                        #pragma unroll
                        for (int mt = 0; mt < 2; mt++) {
                            mma16816(acc[mt][2*ntp],   afl[mt], bh[0], bh[1]);
                            mma16816(acc[mt][2*ntp+1], afl[mt], bh[2], bh[3]);
                        }
                    }
                }
            }
        }

        // Epilogue
        #pragma unroll
        for (int mt = 0; mt < 2; mt++) {
            #pragma unroll
            for (int nt = 0; nt < 8; nt++) {
                int c = n_blk + wc * 64 + nt * 8 + 2 * (lane & 3);
                float b0 = bias[c], b1 = bias[c + 1];
                int hh = c >> 6, dd = c & 63;
                #pragma unroll
                for (int hf = 0; hf < 2; hf++) {
                    int rl = wr * 32 + mt * 16 + (lane >> 2) + hf * 8;
                    float v0 = acc[mt][nt][hf * 2 + 0] + b0;
                    float v1 = acc[mt][nt][hf * 2 + 1] + b1;
                    if (z == 0) {
                        int rg = m_blk + rl;
                        int batch = rg >> 11, s = rg & 2047;
                        size_t idx = (((size_t)batch * H_ + hh) * S_ + s) * 64 + dd;
                        v0 *= SCALE2; v1 *= SCALE2;
                        __half h0 = __float2half_rn(v0), h1 = __float2half_rn(v1);
                        __half l0 = __float2half_rn(v0 - __half2float(h0));
                        __half l1 = __float2half_rn(v1 - __half2float(h1));
                        *(__half2*)&g_qh_hi[idx] = __halves2half2(h0, h1);
                        *(__half2*)&g_qh_lo[idx] = __halves2half2(l0, l1);
                    } else {
                        int j = j0 + rl;
                        size_t idx = (((size_t)bb * H_ + hh) * S_ + j) * 64 + dd;
                        if (z == 1) *(__half2*)&g_kc[idx] = __floats2half2_rn(v0, v1);
                        else        *(__half2*)&g_vc[idx] = __floats2half2_rn(v0, v1);
                    }
                }
            }
        }
        __syncthreads();   // all warps done with smem before next tile's loads
    }
}

// ---------------------------------------------------------------------------
// Kernel 2: PERSISTENT flash attention over COMPACTED keys (R13 body).
// ---------------------------------------------------------------------------
constexpr int KH_OFF = 0;
constexpr int VT_OFF = 18432;
constexpr int QH_OFF = 0;
constexpr int QL_OFF = 18432;
constexpr int ATTN_BODY = 36864;
constexpr int ATTN_SMEM = ATTN_BODY + 16;
constexpr int TSTRIDE = 4608;

__global__ __launch_bounds__(256, 2) void attn_mma(
    const float* __restrict__ qin,
    float*       __restrict__ out)
{
    extern __shared__ char smraw[];
    __half* Kh = (__half*)(smraw + KH_OFF);
    __half* Vt = (__half*)(smraw + VT_OFF);
    __half* Qh = (__half*)(smraw + QH_OFF);
    __half* Ql = (__half*)(smraw + QL_OFF);
    int* wslot = (int*)(smraw + ATTN_BODY);

    const int tid  = threadIdx.x;
    const int lane = tid & 31;
    const int warp = tid >> 5;
    const uint32_t ONESF = 0x3C003C00u;

    for (;;) {
        if (tid == 0) *wslot = (int)atomicAdd(&g_ctr1, 1u);
        __syncthreads();
        const int t = *wslot;
        __syncthreads();
        if (t >= ATTN_NT) break;

        const int b  = t >> 8;
        const int h  = (t >> 4) & 15;
        const int q0 = (t & 15) * 128;

        const size_t head = ((size_t)b * H_ + h) * S_ * 64;
        const int n_cnt = g_cnt[b];
        const int ntile = (n_cnt + 63) >> 6;

        auto load_tile = [&](int kt, int buf) {
            const int kb = kt * 64;
            #pragma unroll
            for (int i = 0; i < 2; i++) {
                int idx = tid * 2 + i;
                int r = idx >> 3, c = (idx & 7) * 8;
                size_t g = head + (size_t)(kb + r) * 64 + c;
                CP16(smaddr(Kh + buf * TSTRIDE + r * 72 + c), g_kc + g);
                CP16(smaddr(Vt + buf * TSTRIDE + r * 72 + c), g_vc + g);
            }
            CPC();
        };

        for (int i = tid; i < 1024; i += 256) {
            int r = i >> 3, c = (i & 7) * 8;
            size_t g = head + (size_t)(q0 + r) * 64 + c;
            CP16(smaddr(Qh + r * 72 + c), g_qh_hi + g);
            CP16(smaddr(Ql + r * 72 + c), g_qh_lo + g);
        }
        CPC(); CPW(0);
        __syncthreads();

        uint32_t qfh[4][4], qfl[4][4];
        const int m0 = warp * 16;
        #pragma unroll
        for (int kc = 0; kc < 4; kc++) {
            int row = m0 + (lane & 15);
            int col = kc * 16 + (lane >> 4) * 8;
            ldsm_x4(qfh[kc], smaddr(Qh + row * 72 + col));
            ldsm_x4(qfl[kc], smaddr(Ql + row * 72 + col));
        }
        __syncthreads();
        load_tile(0, 0);

        float m_i[2] = {-3.0e38f, -3.0e38f};
        float o[9][4];
        #pragma unroll
        for (int nt = 0; nt < 9; nt++)
            #pragma unroll
            for (int e = 0; e < 4; e++) o[nt][e] = 0.0f;

        for (int kt = 0; kt < ntile; kt++) {
            const int buf = kt & 1;
            CPW(0);
            __syncthreads();
            if (kt + 1 < ntile) load_tile(kt + 1, buf ^ 1);

            float s[8][4];
            #pragma unroll
            for (int nt = 0; nt < 8; nt++)
                #pragma unroll
                for (int e = 0; e < 4; e++) s[nt][e] = 0.0f;

            #pragma unroll
            for (int kc = 0; kc < 4; kc++) {
                #pragma unroll
                for (int g = 0; g < 2; g++) {
                    uint32_t bh[2][4];
                    #pragma unroll
                    for (int j = 0; j < 2; j++) {
                        int ntp = g * 2 + j;
                        int row = ntp * 16 + (lane >> 4) * 8 + (lane & 7);
                        int col = kc * 16 + ((lane >> 3) & 1) * 8;
                        ldsm_x4(bh[j], smaddr(Kh + buf * TSTRIDE + row * 72 + col));
                    }
                    #pragma unroll
                    for (int j = 0; j < 2; j++) {
                        int ntp = g * 2 + j;
                        mma16816(s[2*ntp],   qfh[kc], bh[j][0], bh[j][1]);
                        mma16816(s[2*ntp+1], qfh[kc], bh[j][2], bh[j][3]);
                    }
                    #pragma unroll
                    for (int j = 0; j < 2; j++) {
                        int ntp = g * 2 + j;
                        mma16816(s[2*ntp],   qfl[kc], bh[j][0], bh[j][1]);
                        mma16816(s[2*ntp+1], qfl[kc], bh[j][2], bh[j][3]);
                    }
                }
            }

            const int cbase = kt * 64 + 2 * (lane & 3);
            #pragma unroll
            for (int nt = 0; nt < 8; nt++) {
                int c0 = cbase + nt * 8;
                if (c0 >= n_cnt)     { s[nt][0] = NEG; s[nt][2] = NEG; }
                if (c0 + 1 >= n_cnt) { s[nt][1] = NEG; s[nt][3] = NEG; }
            }

            float mx0 = -3.0e38f, mx1 = -3.0e38f;
            #pragma unroll
            for (int nt = 0; nt < 8; nt++) {
                mx0 = fmaxf(mx0, fmaxf(s[nt][0], s[nt][1]));
                mx1 = fmaxf(mx1, fmaxf(s[nt][2], s[nt][3]));
            }
            mx0 = fmaxf(mx0, __shfl_xor_sync(0xffffffffu, mx0, 1));
            mx0 = fmaxf(mx0, __shfl_xor_sync(0xffffffffu, mx0, 2));
            mx1 = fmaxf(mx1, __shfl_xor_sync(0xffffffffu, mx1, 1));
            mx1 = fmaxf(mx1, __shfl_xor_sync(0xffffffffu, mx1, 2));
            float mn0 = fmaxf(fmaxf(m_i[0], mx0), -1.0e8f);
            float mn1 = fmaxf(fmaxf(m_i[1], mx1), -1.0e8f);
            float sc0 = ex2f(m_i[0] - mn0), sc1 = ex2f(m_i[1] - mn1);
            m_i[0] = mn0; m_i[1] = mn1;

            uint32_t p[8][2];
            #pragma unroll
            for (int nt = 0; nt < 8; nt++) {
                p[nt][0] = ex2h2(s[nt][0] - mn0, s[nt][1] - mn0);
                p[nt][1] = ex2h2(s[nt][2] - mn1, s[nt][3] - mn1);
            }

            #pragma unroll
            for (int nt = 0; nt < 9; nt++) {
                o[nt][0] *= sc0; o[nt][1] *= sc0;
                o[nt][2] *= sc1; o[nt][3] *= sc1;
            }

            #pragma unroll
            for (int kc = 0; kc < 4; kc++) {
                uint32_t a[4] = { p[2*kc][0], p[2*kc][1], p[2*kc+1][0], p[2*kc+1][1] };
                #pragma unroll
                for (int g = 0; g < 2; g++) {
                    uint32_t bv[2][4];
                    #pragma unroll
                    for (int j = 0; j < 2; j++) {
                        int ntp = g * 2 + j;
                        int row = kc * 16 + (lane & 15);
                        int col = ntp * 16 + (lane >> 4) * 8;
                        ldsm_x4_t(bv[j], smaddr(Vt + buf * TSTRIDE + row * 72 + col));
                    }
                    #pragma unroll
                    for (int j = 0; j < 2; j++) {
                        int ntp = g * 2 + j;
                        mma16816(o[2*ntp],   a, bv[j][0], bv[j][1]);
                        mma16816(o[2*ntp+1], a, bv[j][2], bv[j][3]);
                    }
                }
                mma16816(o[8], a, ONESF, ONESF);
            }
        }

        float inv0 = 1.0f / o[8][0], inv1 = 1.0f / o[8][2];
        int r0 = q0 + warp * 16 + (lane >> 2);
        int r1 = r0 + 8;
        #pragma unroll
        for (int nt = 0; nt < 8; nt++) {
            int c = h * 64 + nt * 8 + 2 * (lane & 3);
            size_t i0 = ((size_t)b * S_ + r0) * (H_ * DV_) + c;
            size_t i1 = ((size_t)b * S_ + r1) * (H_ * DV_) + c;
            float2 q0v = *(const float2*)(qin + i0);
            float2 q1v = *(const float2*)(qin + i1);
            float2 o0, o1;
            o0.x = o[nt][0] * inv0 + q0v.x;
            o0.y = o[nt][1] * inv0 + q0v.y;
            o1.x = o[nt][2] * inv1 + q1v.x;
            o1.y = o[nt][3] * inv1 + q1v.y;
            *(float2*)(out + i0) = o0;
            *(float2*)(out + i1) = o1;
        }
        __syncthreads();   // smem (Q alias region) free before next tile
    }
}

extern "C" void kernel_launch(void* const* d_in, const int* in_sizes, int n_in,
                              void* d_out, int out_size)
{
    (void)in_sizes; (void)n_in; (void)out_size;
    const float* q    = (const float*)d_in[0];
    const float* k    = (const float*)d_in[1];
    const float* v    = (const float*)d_in[2];
    const int*   mask = (const int*)  d_in[3];
    const float* wq   = (const float*)d_in[4];
    const float* bq   = (const float*)d_in[5];
    const float* wk   = (const float*)d_in[6];
    const float* bk   = (const float*)d_in[7];
    const float* wv   = (const float*)d_in[8];
    const float* bv   = (const float*)d_in[9];
    float* out = (float*)d_out;

    static bool attr_set = false;
    if (!attr_set) {
        cudaFuncSetAttribute(proj_mma, cudaFuncAttributeMaxDynamicSharedMemorySize,
                             PROJ_SMEM);
        cudaFuncSetAttribute(attn_mma, cudaFuncAttributeMaxDynamicSharedMemorySize,
                             ATTN_SMEM);
        attr_set = true;
    }

    int prep_blks = 3 * PREP_A_BLKS + 3 * PREP_W_BLKS + 1;
    prep<<<prep_blks, 256>>>(q, k, v, wq, wk, wv, mask);

    proj_mma<<<PERSIST, 256, PROJ_SMEM>>>(bq, bk, bv);

    attn_mma<<<PERSIST, 256, ATTN_SMEM>>>(q, out);
}

// round 16
// speedup vs baseline: 1.0465x; 1.0465x over previous
#include <cuda_runtime.h>
#include <cuda_fp16.h>
#include <cstdint>

constexpr int B_  = 4;
constexpr int S_  = 2048;
constexpr int DM  = 1024;
constexpr int H_  = 16;
constexpr int DK_ = 64;
constexpr int DV_ = 64;
constexpr int ROWS = B_ * S_;
constexpr float SCALE2 = 11.54156003f;   // 8 * log2(e); folded into Q at proj time
constexpr float NEG    = -1000000000.0f;

// Pre-split inputs (hi/lo fp16)
__device__ __half g_ah[3][(size_t)ROWS * DM];
__device__ __half g_al[2][(size_t)ROWS * DM];
__device__ __half g_wh[3][(size_t)DM * DM];
__device__ __half g_wl[2][(size_t)DM * DM];

// Head-major projected tensors (Q pre-scaled by SCALE2)
__device__ __half g_qh_hi[(size_t)B_*H_*S_*DK_];
__device__ __half g_qh_lo[(size_t)B_*H_*S_*DK_];

// Mask compaction + compacted K/V (written directly by proj)
__device__ int    g_idx[B_][S_];
__device__ int    g_cnt[B_];
__device__ __half g_kc[(size_t)B_*H_*S_*DK_];
__device__ __half g_vc[(size_t)B_*H_*S_*DV_];

// ---------------------------------------------------------------------------
// primitives
// ---------------------------------------------------------------------------
__device__ __forceinline__ uint32_t smaddr(const void* p) {
    return (uint32_t)__cvta_generic_to_shared(p);
}
__device__ __forceinline__ void ldsm_x4(uint32_t (&r)[4], uint32_t a) {
    asm volatile("ldmatrix.sync.aligned.m8n8.x4.shared.b16 {%0,%1,%2,%3}, [%4];"
                 : "=r"(r[0]), "=r"(r[1]), "=r"(r[2]), "=r"(r[3]) : "r"(a));
}
__device__ __forceinline__ void ldsm_x4_t(uint32_t (&r)[4], uint32_t a) {
    asm volatile("ldmatrix.sync.aligned.m8n8.x4.trans.shared.b16 {%0,%1,%2,%3}, [%4];"
                 : "=r"(r[0]), "=r"(r[1]), "=r"(r[2]), "=r"(r[3]) : "r"(a));
}
__device__ __forceinline__ void mma16816(float (&c)[4], const uint32_t (&a)[4],
                                         uint32_t b0, uint32_t b1) {
    asm volatile(
        "mma.sync.aligned.m16n8k16.row.col.f32.f16.f16.f32 "
        "{%0,%1,%2,%3}, {%4,%5,%6,%7}, {%8,%9}, {%0,%1,%2,%3};"
        : "+f"(c[0]), "+f"(c[1]), "+f"(c[2]), "+f"(c[3])
        : "r"(a[0]), "r"(a[1]), "r"(a[2]), "r"(a[3]), "r"(b0), "r"(b1));
}
__device__ __forceinline__ uint32_t packh2(float x, float y) {
    __half2 h = __floats2half2_rn(x, y);
    return *reinterpret_cast<uint32_t*>(&h);
}
__device__ __forceinline__ float ex2f(float x) {
    float y; asm("ex2.approx.ftz.f32 %0, %1;" : "=f"(y) : "f"(x)); return y;
}
__device__ __forceinline__ uint32_t ex2h2(float a, float b) {
    uint32_t h = packh2(a, b);
    uint32_t r; asm("ex2.approx.f16x2 %0, %1;" : "=r"(r) : "r"(h)); return r;
}
#define CP16(dst, src)   asm volatile("cp.async.cg.shared.global [%0], [%1], 16;\n" :: "r"(dst), "l"(src))
#define CP16CA(dst, src) asm volatile("cp.async.ca.shared.global [%0], [%1], 16;\n" :: "r"(dst), "l"(src))
#define CPC()            asm volatile("cp.async.commit_group;\n")
#define CPW(n)           asm volatile("cp.async.wait_group %0;\n" :: "n"(n))

// ---------------------------------------------------------------------------
// Kernel 0: merged preprocessing — A splits, W splits, mask scan in ONE launch
// ---------------------------------------------------------------------------
__device__ __forceinline__ void split_one(const float* __restrict__ src,
                                          __half* __restrict__ hi,
                                          __half* __restrict__ lo, size_t i)
{
    float4 vv = ((const float4*)src)[i];
    float f[4] = {vv.x, vv.y, vv.z, vv.w};
    __half h[4], l[4];
    #pragma unroll
    for (int e = 0; e < 4; e++) {
        h[e] = __float2half_rn(f[e]);
        l[e] = __float2half_rn(f[e] - __half2float(h[e]));
    }
    uint2 ph, pl;
    ph.x = (uint32_t)__half_as_ushort(h[0]) | ((uint32_t)__half_as_ushort(h[1]) << 16);
    ph.y = (uint32_t)__half_as_ushort(h[2]) | ((uint32_t)__half_as_ushort(h[3]) << 16);
    pl.x = (uint32_t)__half_as_ushort(l[0]) | ((uint32_t)__half_as_ushort(l[1]) << 16);
    pl.y = (uint32_t)__half_as_ushort(l[2]) | ((uint32_t)__half_as_ushort(l[3]) << 16);
    ((uint2*)hi)[i] = ph;
    if (lo) ((uint2*)lo)[i] = pl;
}

constexpr int PREP_A_BLKS = (ROWS * DM / 4) / 256;
constexpr int PREP_W_BLKS = (DM * DM / 4) / 256;

__global__ __launch_bounds__(256) void prep(
    const float* __restrict__ q,  const float* __restrict__ k,  const float* __restrict__ v,
    const float* __restrict__ wq, const float* __restrict__ wk, const float* __restrict__ wv,
    const int* __restrict__ mask)
{
    const int bid = blockIdx.x;
    const int tid = threadIdx.x;
    if (bid < 3 * PREP_A_BLKS) {
        int z = bid / PREP_A_BLKS;
        size_t i = (size_t)(bid % PREP_A_BLKS) * 256 + tid;
        const float* src = (z == 0) ? q : (z == 1) ? k : v;
        split_one(src, g_ah[z], (z < 2) ? g_al[z] : nullptr, i);
    } else if (bid < 3 * PREP_A_BLKS + 3 * PREP_W_BLKS) {
        int idx = bid - 3 * PREP_A_BLKS;
        int z = idx / PREP_W_BLKS;
        size_t i = (size_t)(idx % PREP_W_BLKS) * 256 + tid;
        const float* src = (z == 0) ? wq : (z == 1) ? wk : wv;
        split_one(src, g_wh[z], (z < 2) ? g_wl[z] : nullptr, i);
    } else if (tid < 128) {
        const int bw   = tid >> 5;
        const int lane = tid & 31;
        const int* mrow = mask + (size_t)bw * S_;
        int running = 0;
        for (int s0 = 0; s0 < S_; s0 += 32) {
            int m = mrow[s0 + lane];
            unsigned bal = __ballot_sync(0xffffffffu, m != 0);
            int pre = __popc(bal & ((1u << lane) - 1u));
            if (m != 0) g_idx[bw][running + pre] = s0 + lane;
            running += __popc(bal);
        }
        if (lane == 0) g_cnt[bw] = running;
        for (int j = running + lane; j < S_; j += 32) g_idx[bw][j] = 0;
    }
}

// ---------------------------------------------------------------------------
// Kernel 1: projection GEMM (R13 champion). A loads via cp.async.ca —
// consecutive CTAs on an SM share the same A rows -> L1 hits.
// ---------------------------------------------------------------------------
struct ProjSmem {
    __half Ah[2][128][40];
    __half Al[2][128][40];
    __half Wh[2][32][136];
    __half Wl[2][32][136];
};

__global__ __launch_bounds__(256, 2) void proj_mma(
    const float* __restrict__ bq, const float* __restrict__ bk, const float* __restrict__ bv)
{
    const int z = blockIdx.z;

    int bb = 0, j0 = 0, m_blk = 0;
    if (z == 0) {
        m_blk = blockIdx.y * 128;
    } else {
        bb = blockIdx.y >> 4;
        j0 = (blockIdx.y & 15) * 128;
        int npad = (g_cnt[bb] + 63) & ~63;
        if (j0 >= npad) return;
    }

    extern __shared__ char smraw[];
    ProjSmem& S = *reinterpret_cast<ProjSmem*>(smraw);

    const __half* Agh = g_ah[z];
    const __half* Agl = (z < 2) ? g_al[z] : g_ah[z];
    const __half* Wgh = g_wh[z];
    const __half* Wgl = (z < 2) ? g_wl[z] : g_wh[z];
    const float* bias = (z == 0) ? bq : (z == 1) ? bk : bv;

    const int tid  = threadIdx.x;
    const int lane = tid & 31;
    const int warp = tid >> 5;
    const int wr = warp >> 1, wc = warp & 1;
    const int n_blk = blockIdx.x * 128;

    const int ar = tid >> 1;
    size_t arow_off;
    if (z == 0) arow_off = (size_t)(m_blk + ar) * DM;
    else        arow_off = ((size_t)bb * S_ + g_idx[bb][j0 + ar]) * DM;

    float acc[2][8][4];
    #pragma unroll
    for (int mt = 0; mt < 2; mt++)
        #pragma unroll
        for (int nt = 0; nt < 8; nt++)
            #pragma unroll
            for (int e = 0; e < 4; e++) acc[mt][nt][e] = 0.0f;

    auto load_tile = [&](int kt, int buf) {
        const int k0 = kt * 32;
        #pragma unroll
        for (int i = 0; i < 2; i++) {
            int ac = ((tid & 1) * 2 + i) * 8;
            size_t aoff = arow_off + k0 + ac;
            CP16CA(smaddr(&S.Ah[buf][ar][ac]), Agh + aoff);
            if (z < 2) CP16CA(smaddr(&S.Al[buf][ar][ac]), Agl + aoff);
        }
        #pragma unroll
        for (int i = 0; i < 2; i++) {
            int idx = tid * 2 + i;
            int wrow = idx >> 4, wcol = (idx & 15) * 8;
            size_t woff = (size_t)(k0 + wrow) * DM + n_blk + wcol;
            CP16(smaddr(&S.Wh[buf][wrow][wcol]), Wgh + woff);
            if (z < 2) CP16(smaddr(&S.Wl[buf][wrow][wcol]), Wgl + woff);
        }
        CPC();
    };

    load_tile(0, 0);

    for (int kt = 0; kt < DM / 32; kt++) {
        const int buf = kt & 1;
        CPW(0);
        __syncthreads();
        if (kt + 1 < DM / 32) load_tile(kt + 1, buf ^ 1);

        #pragma unroll
        for (int kc = 0; kc < 2; kc++) {
            uint32_t afh[2][4], afl[2][4];
            #pragma unroll
            for (int mt = 0; mt < 2; mt++) {
                int row = wr * 32 + mt * 16 + (lane & 15);
                int col = kc * 16 + (lane >> 4) * 8;
                ldsm_x4(afh[mt], smaddr(&S.Ah[buf][row][col]));
                if (z < 2) ldsm_x4(afl[mt], smaddr(&S.Al[buf][row][col]));
            }
            #pragma unroll
            for (int ntp = 0; ntp < 4; ntp++) {
                uint32_t bh[4], bl[4];
                int krow = kc * 16 + (lane & 15);
                int ncol = wc * 64 + ntp * 16 + (lane >> 4) * 8;
                ldsm_x4_t(bh, smaddr(&S.Wh[buf][krow][ncol]));
                if (z < 2) ldsm_x4_t(bl, smaddr(&S.Wl[buf][krow][ncol]));
                // phase 1: hh
                #pragma unroll
                for (int mt = 0; mt < 2; mt++) {
                    mma16816(acc[mt][2*ntp],   afh[mt], bh[0], bh[1]);
                    mma16816(acc[mt][2*ntp+1], afh[mt], bh[2], bh[3]);
                }
                if (z < 2) {
                    // phase 2: hl
                    #pragma unroll
                    for (int mt = 0; mt < 2; mt++) {
                        mma16816(acc[mt][2*ntp],   afh[mt], bl[0], bl[1]);
                        mma16816(acc[mt][2*ntp+1], afh[mt], bl[2], bl[3]);
                    }
                    // phase 3: lh
                    #pragma unroll
                    for (int mt = 0; mt < 2; mt++) {
                        mma16816(acc[mt][2*ntp],   afl[mt], bh[0], bh[1]);
                        mma16816(acc[mt][2*ntp+1], afl[mt], bh[2], bh[3]);
                    }
                }
            }
        }
    }

    // Epilogue
    #pragma unroll
    for (int mt = 0; mt < 2; mt++) {
        #pragma unroll
        for (int nt = 0; nt < 8; nt++) {
            int c = n_blk + wc * 64 + nt * 8 + 2 * (lane & 3);
            float b0 = bias[c], b1 = bias[c + 1];
            int hh = c >> 6, dd = c & 63;
            #pragma unroll
            for (int hf = 0; hf < 2; hf++) {
                int rl = wr * 32 + mt * 16 + (lane >> 2) + hf * 8;
                float v0 = acc[mt][nt][hf * 2 + 0] + b0;
                float v1 = acc[mt][nt][hf * 2 + 1] + b1;
                if (z == 0) {
                    int rg = m_blk + rl;
                    int batch = rg >> 11, s = rg & 2047;
                    size_t idx = (((size_t)batch * H_ + hh) * S_ + s) * 64 + dd;
                    v0 *= SCALE2; v1 *= SCALE2;
                    __half h0 = __float2half_rn(v0), h1 = __float2half_rn(v1);
                    __half l0 = __float2half_rn(v0 - __half2float(h0));
                    __half l1 = __float2half_rn(v1 - __half2float(h1));
                    *(__half2*)&g_qh_hi[idx] = __halves2half2(h0, h1);
                    *(__half2*)&g_qh_lo[idx] = __halves2half2(l0, l1);
                } else {
                    int j = j0 + rl;
                    size_t idx = (((size_t)bb * H_ + hh) * S_ + j) * 64 + dd;
                    if (z == 1) *(__half2*)&g_kc[idx] = __floats2half2_rn(v0, v1);
                    else        *(__half2*)&g_vc[idx] = __floats2half2_rn(v0, v1);
                }
            }
        }
    }
}

// ---------------------------------------------------------------------------
// Kernel 2: flash attention over COMPACTED keys (R13) + bit-identical
// skip-rescale when no row max changed this tile.
// ---------------------------------------------------------------------------
constexpr int KH_OFF = 0;
constexpr int VT_OFF = 18432;
constexpr int QH_OFF = 0;
constexpr int QL_OFF = 18432;
constexpr int ATTN_SMEM = 36864;
constexpr int TSTRIDE = 4608;

__global__ __launch_bounds__(256, 2) void attn_mma(
    const float* __restrict__ qin,
    float*       __restrict__ out)
{
    extern __shared__ char smraw[];
    __half* Kh = (__half*)(smraw + KH_OFF);
    __half* Vt = (__half*)(smraw + VT_OFF);
    __half* Qh = (__half*)(smraw + QH_OFF);
    __half* Ql = (__half*)(smraw + QL_OFF);

    const int tid  = threadIdx.x;
    const int lane = tid & 31;
    const int warp = tid >> 5;
    const int b  = blockIdx.z;
    const int h  = blockIdx.y;
    const int q0 = blockIdx.x * 128;

    const size_t head = ((size_t)b * H_ + h) * S_ * 64;
    const int n_cnt = g_cnt[b];
    const int ntile = (n_cnt + 63) >> 6;
    const uint32_t ONESF = 0x3C003C00u;

    auto load_tile = [&](int kt, int buf) {
        const int kb = kt * 64;
        #pragma unroll
        for (int i = 0; i < 2; i++) {
            int idx = tid * 2 + i;
            int r = idx >> 3, c = (idx & 7) * 8;
            size_t g = head + (size_t)(kb + r) * 64 + c;
            CP16(smaddr(Kh + buf * TSTRIDE + r * 72 + c), g_kc + g);
            CP16(smaddr(Vt + buf * TSTRIDE + r * 72 + c), g_vc + g);
        }
        CPC();
    };

    for (int i = tid; i < 1024; i += 256) {
        int r = i >> 3, c = (i & 7) * 8;
        size_t g = head + (size_t)(q0 + r) * 64 + c;
        CP16(smaddr(Qh + r * 72 + c), g_qh_hi + g);
        CP16(smaddr(Ql + r * 72 + c), g_qh_lo + g);
    }
    CPC(); CPW(0);
    __syncthreads();

    uint32_t qfh[4][4], qfl[4][4];
    const int m0 = warp * 16;
    #pragma unroll
    for (int kc = 0; kc < 4; kc++) {
        int row = m0 + (lane & 15);
        int col = kc * 16 + (lane >> 4) * 8;
        ldsm_x4(qfh[kc], smaddr(Qh + row * 72 + col));
        ldsm_x4(qfl[kc], smaddr(Ql + row * 72 + col));
    }
    __syncthreads();
    load_tile(0, 0);

    float m_i[2] = {-3.0e38f, -3.0e38f};
    float o[9][4];
    #pragma unroll
    for (int nt = 0; nt < 9; nt++)
        #pragma unroll
        for (int e = 0; e < 4; e++) o[nt][e] = 0.0f;

    for (int kt = 0; kt < ntile; kt++) {
        const int buf = kt & 1;
        CPW(0);
        __syncthreads();
        if (kt + 1 < ntile) load_tile(kt + 1, buf ^ 1);

        float s[8][4];
        #pragma unroll
        for (int nt = 0; nt < 8; nt++)
            #pragma unroll
            for (int e = 0; e < 4; e++) s[nt][e] = 0.0f;

        #pragma unroll
        for (int kc = 0; kc < 4; kc++) {
            #pragma unroll
            for (int g = 0; g < 2; g++) {
                uint32_t bh[2][4];
                #pragma unroll
                for (int j = 0; j < 2; j++) {
                    int ntp = g * 2 + j;
                    int row = ntp * 16 + (lane >> 4) * 8 + (lane & 7);
                    int col = kc * 16 + ((lane >> 3) & 1) * 8;
                    ldsm_x4(bh[j], smaddr(Kh + buf * TSTRIDE + row * 72 + col));
                }
                #pragma unroll
                for (int j = 0; j < 2; j++) {
                    int ntp = g * 2 + j;
                    mma16816(s[2*ntp],   qfh[kc], bh[j][0], bh[j][1]);
                    mma16816(s[2*ntp+1], qfh[kc], bh[j][2], bh[j][3]);
                }
                #pragma unroll
                for (int j = 0; j < 2; j++) {
                    int ntp = g * 2 + j;
                    mma16816(s[2*ntp],   qfl[kc], bh[j][0], bh[j][1]);
                    mma16816(s[2*ntp+1], qfl[kc], bh[j][2], bh[j][3]);
                }
            }
        }

        const int cbase = kt * 64 + 2 * (lane & 3);
        #pragma unroll
        for (int nt = 0; nt < 8; nt++) {
            int c0 = cbase + nt * 8;
            if (c0 >= n_cnt)     { s[nt][0] = NEG; s[nt][2] = NEG; }
            if (c0 + 1 >= n_cnt) { s[nt][1] = NEG; s[nt][3] = NEG; }
        }

        float mx0 = -3.0e38f, mx1 = -3.0e38f;
        #pragma unroll
        for (int nt = 0; nt < 8; nt++) {
            mx0 = fmaxf(mx0, fmaxf(s[nt][0], s[nt][1]));
            mx1 = fmaxf(mx1, fmaxf(s[nt][2], s[nt][3]));
        }
        mx0 = fmaxf(mx0, __shfl_xor_sync(0xffffffffu, mx0, 1));
        mx0 = fmaxf(mx0, __shfl_xor_sync(0xffffffffu, mx0, 2));
        mx1 = fmaxf(mx1, __shfl_xor_sync(0xffffffffu, mx1, 1));
        mx1 = fmaxf(mx1, __shfl_xor_sync(0xffffffffu, mx1, 2));
        float mn0 = fmaxf(fmaxf(m_i[0], mx0), -1.0e8f);
        float mn1 = fmaxf(fmaxf(m_i[1], mx1), -1.0e8f);

        // skip-rescale: if NO row in the warp raised its max, sc==1 exactly
        // and the rescale multiplies are by 1.0 -> bit-identical to skip.
        bool nochange = (mn0 == m_i[0]) && (mn1 == m_i[1]);
        if (!__all_sync(0xffffffffu, nochange)) {
            float sc0 = ex2f(m_i[0] - mn0), sc1 = ex2f(m_i[1] - mn1);
            #pragma unroll
            for (int nt = 0; nt < 9; nt++) {
                o[nt][0] *= sc0; o[nt][1] *= sc0;
                o[nt][2] *= sc1; o[nt][3] *= sc1;
            }
            m_i[0] = mn0; m_i[1] = mn1;
        }

        uint32_t p[8][2];
        #pragma unroll
        for (int nt = 0; nt < 8; nt++) {
            p[nt][0] = ex2h2(s[nt][0] - m_i[0], s[nt][1] - m_i[0]);
            p[nt][1] = ex2h2(s[nt][2] - m_i[1], s[nt][3] - m_i[1]);
        }

        #pragma unroll
        for (int kc = 0; kc < 4; kc++) {
            uint32_t a[4] = { p[2*kc][0], p[2*kc][1], p[2*kc+1][0], p[2*kc+1][1] };
            #pragma unroll
            for (int g = 0; g < 2; g++) {
                uint32_t bv[2][4];
                #pragma unroll
                for (int j = 0; j < 2; j++) {
                    int ntp = g * 2 + j;
                    int row = kc * 16 + (lane & 15);
                    int col = ntp * 16 + (lane >> 4) * 8;
                    ldsm_x4_t(bv[j], smaddr(Vt + buf * TSTRIDE + row * 72 + col));
                }
                #pragma unroll
                for (int j = 0; j < 2; j++) {
                    int ntp = g * 2 + j;
                    mma16816(o[2*ntp],   a, bv[j][0], bv[j][1]);
                    mma16816(o[2*ntp+1], a, bv[j][2], bv[j][3]);
                }
            }
            mma16816(o[8], a, ONESF, ONESF);
        }
    }

    float inv0 = 1.0f / o[8][0], inv1 = 1.0f / o[8][2];
    int r0 = q0 + warp * 16 + (lane >> 2);
    int r1 = r0 + 8;
    #pragma unroll
    for (int nt = 0; nt < 8; nt++) {
        int c = h * 64 + nt * 8 + 2 * (lane & 3);
        size_t i0 = ((size_t)b * S_ + r0) * (H_ * DV_) + c;
        size_t i1 = ((size_t)b * S_ + r1) * (H_ * DV_) + c;
        float2 q0v = *(const float2*)(qin + i0);
        float2 q1v = *(const float2*)(qin + i1);
        float2 o0, o1;
        o0.x = o[nt][0] * inv0 + q0v.x;
        o0.y = o[nt][1] * inv0 + q0v.y;
        o1.x = o[nt][2] * inv1 + q1v.x;
        o1.y = o[nt][3] * inv1 + q1v.y;
        *(float2*)(out + i0) = o0;
        *(float2*)(out + i1) = o1;
    }
}

extern "C" void kernel_launch(void* const* d_in, const int* in_sizes, int n_in,
                              void* d_out, int out_size)
{
    (void)in_sizes; (void)n_in; (void)out_size;
    const float* q    = (const float*)d_in[0];
    const float* k    = (const float*)d_in[1];
    const float* v    = (const float*)d_in[2];
    const int*   mask = (const int*)  d_in[3];
    const float* wq   = (const float*)d_in[4];
    const float* bq   = (const float*)d_in[5];
    const float* wk   = (const float*)d_in[6];
    const float* bk   = (const float*)d_in[7];
    const float* wv   = (const float*)d_in[8];
    const float* bv   = (const float*)d_in[9];
    float* out = (float*)d_out;

    static bool attr_set = false;
    if (!attr_set) {
        cudaFuncSetAttribute(proj_mma, cudaFuncAttributeMaxDynamicSharedMemorySize,
                             (int)sizeof(ProjSmem));
        attr_set = true;
    }

    int prep_blks = 3 * PREP_A_BLKS + 3 * PREP_W_BLKS + 1;
    prep<<<prep_blks, 256>>>(q, k, v, wq, wk, wv, mask);

    dim3 pg(DM / 128, ROWS / 128, 3);   // (8, 64, 3); z>0 early-exit past count
    proj_mma<<<pg, 256, sizeof(ProjSmem)>>>(bq, bk, bv);

    dim3 ag(S_ / 128, H_, B_);
    attn_mma<<<ag, 256, ATTN_SMEM>>>(q, out);
}

// round 17
// speedup vs baseline: 1.0700x; 1.0225x over previous
#include <cuda_runtime.h>
#include <cuda_fp16.h>
#include <cstdint>

constexpr int B_  = 4;
constexpr int S_  = 2048;
constexpr int DM  = 1024;
constexpr int H_  = 16;
constexpr int DK_ = 64;
constexpr int DV_ = 64;
constexpr int ROWS = B_ * S_;
constexpr float SCALE2 = 11.54156003f;   // 8 * log2(e); folded into Q at proj time
constexpr float NEG    = -1000000000.0f;

// Pre-split inputs (hi/lo fp16)
__device__ __half g_ah[3][(size_t)ROWS * DM];
__device__ __half g_al[2][(size_t)ROWS * DM];
__device__ __half g_wh[3][(size_t)DM * DM];
__device__ __half g_wl[2][(size_t)DM * DM];

// Head-major projected tensors (Q pre-scaled by SCALE2)
__device__ __half g_qh_hi[(size_t)B_*H_*S_*DK_];
__device__ __half g_qh_lo[(size_t)B_*H_*S_*DK_];

// Mask compaction + compacted K/V (written directly by proj)
__device__ int    g_idx[B_][S_];
__device__ int    g_cnt[B_];
__device__ __half g_kc[(size_t)B_*H_*S_*DK_];
__device__ __half g_vc[(size_t)B_*H_*S_*DV_];

// ---------------------------------------------------------------------------
// primitives
// ---------------------------------------------------------------------------
__device__ __forceinline__ uint32_t smaddr(const void* p) {
    return (uint32_t)__cvta_generic_to_shared(p);
}
__device__ __forceinline__ void ldsm_x4(uint32_t (&r)[4], uint32_t a) {
    asm volatile("ldmatrix.sync.aligned.m8n8.x4.shared.b16 {%0,%1,%2,%3}, [%4];"
                 : "=r"(r[0]), "=r"(r[1]), "=r"(r[2]), "=r"(r[3]) : "r"(a));
}
__device__ __forceinline__ void ldsm_x4_t(uint32_t (&r)[4], uint32_t a) {
    asm volatile("ldmatrix.sync.aligned.m8n8.x4.trans.shared.b16 {%0,%1,%2,%3}, [%4];"
                 : "=r"(r[0]), "=r"(r[1]), "=r"(r[2]), "=r"(r[3]) : "r"(a));
}
__device__ __forceinline__ void mma16816(float (&c)[4], const uint32_t (&a)[4],
                                         uint32_t b0, uint32_t b1) {
    asm volatile(
        "mma.sync.aligned.m16n8k16.row.col.f32.f16.f16.f32 "
        "{%0,%1,%2,%3}, {%4,%5,%6,%7}, {%8,%9}, {%0,%1,%2,%3};"
        : "+f"(c[0]), "+f"(c[1]), "+f"(c[2]), "+f"(c[3])
        : "r"(a[0]), "r"(a[1]), "r"(a[2]), "r"(a[3]), "r"(b0), "r"(b1));
}
__device__ __forceinline__ uint32_t packh2(float x, float y) {
    __half2 h = __floats2half2_rn(x, y);
    return *reinterpret_cast<uint32_t*>(&h);
}
__device__ __forceinline__ float ex2f(float x) {
    float y; asm("ex2.approx.ftz.f32 %0, %1;" : "=f"(y) : "f"(x)); return y;
}
__device__ __forceinline__ uint32_t ex2h2(float a, float b) {
    uint32_t h = packh2(a, b);
    uint32_t r; asm("ex2.approx.f16x2 %0, %1;" : "=r"(r) : "r"(h)); return r;
}
#define CP16(dst, src)   asm volatile("cp.async.cg.shared.global [%0], [%1], 16;\n" :: "r"(dst), "l"(src))
#define CP16CA(dst, src) asm volatile("cp.async.ca.shared.global [%0], [%1], 16;\n" :: "r"(dst), "l"(src))
#define CPC()            asm volatile("cp.async.commit_group;\n")
#define CPW(n)           asm volatile("cp.async.wait_group %0;\n" :: "n"(n))

// ---------------------------------------------------------------------------
// Kernel 0: merged preprocessing — A splits, W splits, mask scan in ONE launch
// ---------------------------------------------------------------------------
__device__ __forceinline__ void split_one(const float* __restrict__ src,
                                          __half* __restrict__ hi,
                                          __half* __restrict__ lo, size_t i)
{
    float4 vv = ((const float4*)src)[i];
    float f[4] = {vv.x, vv.y, vv.z, vv.w};
    __half h[4], l[4];
    #pragma unroll
    for (int e = 0; e < 4; e++) {
        h[e] = __float2half_rn(f[e]);
        l[e] = __float2half_rn(f[e] - __half2float(h[e]));
    }
    uint2 ph, pl;
    ph.x = (uint32_t)__half_as_ushort(h[0]) | ((uint32_t)__half_as_ushort(h[1]) << 16);
    ph.y = (uint32_t)__half_as_ushort(h[2]) | ((uint32_t)__half_as_ushort(h[3]) << 16);
    pl.x = (uint32_t)__half_as_ushort(l[0]) | ((uint32_t)__half_as_ushort(l[1]) << 16);
    pl.y = (uint32_t)__half_as_ushort(l[2]) | ((uint32_t)__half_as_ushort(l[3]) << 16);
    ((uint2*)hi)[i] = ph;
    if (lo) ((uint2*)lo)[i] = pl;
}

constexpr int PREP_A_BLKS = (ROWS * DM / 4) / 256;
constexpr int PREP_W_BLKS = (DM * DM / 4) / 256;

__global__ __launch_bounds__(256) void prep(
    const float* __restrict__ q,  const float* __restrict__ k,  const float* __restrict__ v,
    const float* __restrict__ wq, const float* __restrict__ wk, const float* __restrict__ wv,
    const int* __restrict__ mask)
{
    const int bid = blockIdx.x;
    const int tid = threadIdx.x;
    if (bid < 3 * PREP_A_BLKS) {
        int z = bid / PREP_A_BLKS;
        size_t i = (size_t)(bid % PREP_A_BLKS) * 256 + tid;
        const float* src = (z == 0) ? q : (z == 1) ? k : v;
        split_one(src, g_ah[z], (z < 2) ? g_al[z] : nullptr, i);
    } else if (bid < 3 * PREP_A_BLKS + 3 * PREP_W_BLKS) {
        int idx = bid - 3 * PREP_A_BLKS;
        int z = idx / PREP_W_BLKS;
        size_t i = (size_t)(idx % PREP_W_BLKS) * 256 + tid;
        const float* src = (z == 0) ? wq : (z == 1) ? wk : wv;
        split_one(src, g_wh[z], (z < 2) ? g_wl[z] : nullptr, i);
    } else if (tid < 128) {
        const int bw   = tid >> 5;
        const int lane = tid & 31;
        const int* mrow = mask + (size_t)bw * S_;
        int running = 0;
        for (int s0 = 0; s0 < S_; s0 += 32) {
            int m = mrow[s0 + lane];
            unsigned bal = __ballot_sync(0xffffffffu, m != 0);
            int pre = __popc(bal & ((1u << lane) - 1u));
            if (m != 0) g_idx[bw][running + pre] = s0 + lane;
            running += __popc(bal);
        }
        if (lane == 0) g_cnt[bw] = running;
        for (int j = running + lane; j < S_; j += 32) g_idx[bw][j] = 0;
    }
}

// ---------------------------------------------------------------------------
// Kernel 1: projection GEMM (R16 champion). A loads via cp.async.ca.
// ---------------------------------------------------------------------------
struct ProjSmem {
    __half Ah[2][128][40];
    __half Al[2][128][40];
    __half Wh[2][32][136];
    __half Wl[2][32][136];
};

__global__ __launch_bounds__(256, 2) void proj_mma(
    const float* __restrict__ bq, const float* __restrict__ bk, const float* __restrict__ bv)
{
    const int z = blockIdx.z;

    int bb = 0, j0 = 0, m_blk = 0;
    if (z == 0) {
        m_blk = blockIdx.y * 128;
    } else {
        bb = blockIdx.y >> 4;
        j0 = (blockIdx.y & 15) * 128;
        int npad = (g_cnt[bb] + 63) & ~63;
        if (j0 >= npad) return;
    }

    extern __shared__ char smraw[];
    ProjSmem& S = *reinterpret_cast<ProjSmem*>(smraw);

    const __half* Agh = g_ah[z];
    const __half* Agl = (z < 2) ? g_al[z] : g_ah[z];
    const __half* Wgh = g_wh[z];
    const __half* Wgl = (z < 2) ? g_wl[z] : g_wh[z];
    const float* bias = (z == 0) ? bq : (z == 1) ? bk : bv;

    const int tid  = threadIdx.x;
    const int lane = tid & 31;
    const int warp = tid >> 5;
    const int wr = warp >> 1, wc = warp & 1;
    const int n_blk = blockIdx.x * 128;

    const int ar = tid >> 1;
    size_t arow_off;
    if (z == 0) arow_off = (size_t)(m_blk + ar) * DM;
    else        arow_off = ((size_t)bb * S_ + g_idx[bb][j0 + ar]) * DM;

    float acc[2][8][4];
    #pragma unroll
    for (int mt = 0; mt < 2; mt++)
        #pragma unroll
        for (int nt = 0; nt < 8; nt++)
            #pragma unroll
            for (int e = 0; e < 4; e++) acc[mt][nt][e] = 0.0f;

    auto load_tile = [&](int kt, int buf) {
        const int k0 = kt * 32;
        #pragma unroll
        for (int i = 0; i < 2; i++) {
            int ac = ((tid & 1) * 2 + i) * 8;
            size_t aoff = arow_off + k0 + ac;
            CP16CA(smaddr(&S.Ah[buf][ar][ac]), Agh + aoff);
            if (z < 2) CP16CA(smaddr(&S.Al[buf][ar][ac]), Agl + aoff);
        }
        #pragma unroll
        for (int i = 0; i < 2; i++) {
            int idx = tid * 2 + i;
            int wrow = idx >> 4, wcol = (idx & 15) * 8;
            size_t woff = (size_t)(k0 + wrow) * DM + n_blk + wcol;
            CP16(smaddr(&S.Wh[buf][wrow][wcol]), Wgh + woff);
            if (z < 2) CP16(smaddr(&S.Wl[buf][wrow][wcol]), Wgl + woff);
        }
        CPC();
    };

    load_tile(0, 0);

    for (int kt = 0; kt < DM / 32; kt++) {
        const int buf = kt & 1;
        CPW(0);
        __syncthreads();
        if (kt + 1 < DM / 32) load_tile(kt + 1, buf ^ 1);

        #pragma unroll
        for (int kc = 0; kc < 2; kc++) {
            uint32_t afh[2][4], afl[2][4];
            #pragma unroll
            for (int mt = 0; mt < 2; mt++) {
                int row = wr * 32 + mt * 16 + (lane & 15);
                int col = kc * 16 + (lane >> 4) * 8;
                ldsm_x4(afh[mt], smaddr(&S.Ah[buf][row][col]));
                if (z < 2) ldsm_x4(afl[mt], smaddr(&S.Al[buf][row][col]));
            }
            #pragma unroll
            for (int ntp = 0; ntp < 4; ntp++) {
                uint32_t bh[4], bl[4];
                int krow = kc * 16 + (lane & 15);
                int ncol = wc * 64 + ntp * 16 + (lane >> 4) * 8;
                ldsm_x4_t(bh, smaddr(&S.Wh[buf][krow][ncol]));
                if (z < 2) ldsm_x4_t(bl, smaddr(&S.Wl[buf][krow][ncol]));
                // phase 1: hh
                #pragma unroll
                for (int mt = 0; mt < 2; mt++) {
                    mma16816(acc[mt][2*ntp],   afh[mt], bh[0], bh[1]);
                    mma16816(acc[mt][2*ntp+1], afh[mt], bh[2], bh[3]);
                }
                if (z < 2) {
                    // phase 2: hl
                    #pragma unroll
                    for (int mt = 0; mt < 2; mt++) {
                        mma16816(acc[mt][2*ntp],   afh[mt], bl[0], bl[1]);
                        mma16816(acc[mt][2*ntp+1], afh[mt], bl[2], bl[3]);
                    }
                    // phase 3: lh
                    #pragma unroll
                    for (int mt = 0; mt < 2; mt++) {
                        mma16816(acc[mt][2*ntp],   afl[mt], bh[0], bh[1]);
                        mma16816(acc[mt][2*ntp+1], afl[mt], bh[2], bh[3]);
                    }
                }
            }
        }
    }

    // Epilogue
    #pragma unroll
    for (int mt = 0; mt < 2; mt++) {
        #pragma unroll
        for (int nt = 0; nt < 8; nt++) {
            int c = n_blk + wc * 64 + nt * 8 + 2 * (lane & 3);
            float b0 = bias[c], b1 = bias[c + 1];
            int hh = c >> 6, dd = c & 63;
            #pragma unroll
            for (int hf = 0; hf < 2; hf++) {
                int rl = wr * 32 + mt * 16 + (lane >> 2) + hf * 8;
                float v0 = acc[mt][nt][hf * 2 + 0] + b0;
                float v1 = acc[mt][nt][hf * 2 + 1] + b1;
                if (z == 0) {
                    int rg = m_blk + rl;
                    int batch = rg >> 11, s = rg & 2047;
                    size_t idx = (((size_t)batch * H_ + hh) * S_ + s) * 64 + dd;
                    v0 *= SCALE2; v1 *= SCALE2;
                    __half h0 = __float2half_rn(v0), h1 = __float2half_rn(v1);
                    __half l0 = __float2half_rn(v0 - __half2float(h0));
                    __half l1 = __float2half_rn(v1 - __half2float(h1));
                    *(__half2*)&g_qh_hi[idx] = __halves2half2(h0, h1);
                    *(__half2*)&g_qh_lo[idx] = __halves2half2(l0, l1);
                } else {
                    int j = j0 + rl;
                    size_t idx = (((size_t)bb * H_ + hh) * S_ + j) * 64 + dd;
                    if (z == 1) *(__half2*)&g_kc[idx] = __floats2half2_rn(v0, v1);
                    else        *(__half2*)&g_vc[idx] = __floats2half2_rn(v0, v1);
                }
            }
        }
    }
}

// ---------------------------------------------------------------------------
// Kernel 2: flash attention over COMPACTED keys. K/V loads via cp.async.ca —
// co-resident CTAs (adjacent q-tiles, same b,h) stream identical K/V tiles
// and hit in L1. Skip-rescale (bit-identical) retained.
// ---------------------------------------------------------------------------
constexpr int KH_OFF = 0;
constexpr int VT_OFF = 18432;
constexpr int QH_OFF = 0;
constexpr int QL_OFF = 18432;
constexpr int ATTN_SMEM = 36864;
constexpr int TSTRIDE = 4608;

__global__ __launch_bounds__(256, 2) void attn_mma(
    const float* __restrict__ qin,
    float*       __restrict__ out)
{
    extern __shared__ char smraw[];
    __half* Kh = (__half*)(smraw + KH_OFF);
    __half* Vt = (__half*)(smraw + VT_OFF);
    __half* Qh = (__half*)(smraw + QH_OFF);
    __half* Ql = (__half*)(smraw + QL_OFF);

    const int tid  = threadIdx.x;
    const int lane = tid & 31;
    const int warp = tid >> 5;
    const int b  = blockIdx.z;
    const int h  = blockIdx.y;
    const int q0 = blockIdx.x * 128;

    const size_t head = ((size_t)b * H_ + h) * S_ * 64;
    const int n_cnt = g_cnt[b];
    const int ntile = (n_cnt + 63) >> 6;
    const uint32_t ONESF = 0x3C003C00u;

    auto load_tile = [&](int kt, int buf) {
        const int kb = kt * 64;
        #pragma unroll
        for (int i = 0; i < 2; i++) {
            int idx = tid * 2 + i;
            int r = idx >> 3, c = (idx & 7) * 8;
            size_t g = head + (size_t)(kb + r) * 64 + c;
            CP16CA(smaddr(Kh + buf * TSTRIDE + r * 72 + c), g_kc + g);
            CP16CA(smaddr(Vt + buf * TSTRIDE + r * 72 + c), g_vc + g);
        }
        CPC();
    };

    for (int i = tid; i < 1024; i += 256) {
        int r = i >> 3, c = (i & 7) * 8;
        size_t g = head + (size_t)(q0 + r) * 64 + c;
        CP16CA(smaddr(Qh + r * 72 + c), g_qh_hi + g);
        CP16CA(smaddr(Ql + r * 72 + c), g_qh_lo + g);
    }
    CPC(); CPW(0);
    __syncthreads();

    uint32_t qfh[4][4], qfl[4][4];
    const int m0 = warp * 16;
    #pragma unroll
    for (int kc = 0; kc < 4; kc++) {
        int row = m0 + (lane & 15);
        int col = kc * 16 + (lane >> 4) * 8;
        ldsm_x4(qfh[kc], smaddr(Qh + row * 72 + col));
        ldsm_x4(qfl[kc], smaddr(Ql + row * 72 + col));
    }
    __syncthreads();
    load_tile(0, 0);

    float m_i[2] = {-3.0e38f, -3.0e38f};
    float o[9][4];
    #pragma unroll
    for (int nt = 0; nt < 9; nt++)
        #pragma unroll
        for (int e = 0; e < 4; e++) o[nt][e] = 0.0f;

    for (int kt = 0; kt < ntile; kt++) {
        const int buf = kt & 1;
        CPW(0);
        __syncthreads();
        if (kt + 1 < ntile) load_tile(kt + 1, buf ^ 1);

        float s[8][4];
        #pragma unroll
        for (int nt = 0; nt < 8; nt++)
            #pragma unroll
            for (int e = 0; e < 4; e++) s[nt][e] = 0.0f;

        #pragma unroll
        for (int kc = 0; kc < 4; kc++) {
            #pragma unroll
            for (int g = 0; g < 2; g++) {
                uint32_t bh[2][4];
                #pragma unroll
                for (int j = 0; j < 2; j++) {
                    int ntp = g * 2 + j;
                    int row = ntp * 16 + (lane >> 4) * 8 + (lane & 7);
                    int col = kc * 16 + ((lane >> 3) & 1) * 8;
                    ldsm_x4(bh[j], smaddr(Kh + buf * TSTRIDE + row * 72 + col));
                }
                #pragma unroll
                for (int j = 0; j < 2; j++) {
                    int ntp = g * 2 + j;
                    mma16816(s[2*ntp],   qfh[kc], bh[j][0], bh[j][1]);
                    mma16816(s[2*ntp+1], qfh[kc], bh[j][2], bh[j][3]);
                }
                #pragma unroll
                for (int j = 0; j < 2; j++) {
                    int ntp = g * 2 + j;
                    mma16816(s[2*ntp],   qfl[kc], bh[j][0], bh[j][1]);
                    mma16816(s[2*ntp+1], qfl[kc], bh[j][2], bh[j][3]);
                }
            }
        }

        const int cbase = kt * 64 + 2 * (lane & 3);
        #pragma unroll
        for (int nt = 0; nt < 8; nt++) {
            int c0 = cbase + nt * 8;
            if (c0 >= n_cnt)     { s[nt][0] = NEG; s[nt][2] = NEG; }
            if (c0 + 1 >= n_cnt) { s[nt][1] = NEG; s[nt][3] = NEG; }
        }

        float mx0 = -3.0e38f, mx1 = -3.0e38f;
        #pragma unroll
        for (int nt = 0; nt < 8; nt++) {
            mx0 = fmaxf(mx0, fmaxf(s[nt][0], s[nt][1]));
            mx1 = fmaxf(mx1, fmaxf(s[nt][2], s[nt][3]));
        }
        mx0 = fmaxf(mx0, __shfl_xor_sync(0xffffffffu, mx0, 1));
        mx0 = fmaxf(mx0, __shfl_xor_sync(0xffffffffu, mx0, 2));
        mx1 = fmaxf(mx1, __shfl_xor_sync(0xffffffffu, mx1, 1));
        mx1 = fmaxf(mx1, __shfl_xor_sync(0xffffffffu, mx1, 2));
        float mn0 = fmaxf(fmaxf(m_i[0], mx0), -1.0e8f);
        float mn1 = fmaxf(fmaxf(m_i[1], mx1), -1.0e8f);

        bool nochange = (mn0 == m_i[0]) && (mn1 == m_i[1]);
        if (!__all_sync(0xffffffffu, nochange)) {
            float sc0 = ex2f(m_i[0] - mn0), sc1 = ex2f(m_i[1] - mn1);
            #pragma unroll
            for (int nt = 0; nt < 9; nt++) {
                o[nt][0] *= sc0; o[nt][1] *= sc0;
                o[nt][2] *= sc1; o[nt][3] *= sc1;
            }
            m_i[0] = mn0; m_i[1] = mn1;
        }

        uint32_t p[8][2];
        #pragma unroll
        for (int nt = 0; nt < 8; nt++) {
            p[nt][0] = ex2h2(s[nt][0] - m_i[0], s[nt][1] - m_i[0]);
            p[nt][1] = ex2h2(s[nt][2] - m_i[1], s[nt][3] - m_i[1]);
        }

        #pragma unroll
        for (int kc = 0; kc < 4; kc++) {
            uint32_t a[4] = { p[2*kc][0], p[2*kc][1], p[2*kc+1][0], p[2*kc+1][1] };
            #pragma unroll
            for (int g = 0; g < 2; g++) {
                uint32_t bv[2][4];
                #pragma unroll
                for (int j = 0; j < 2; j++) {
                    int ntp = g * 2 + j;
                    int row = kc * 16 + (lane & 15);
                    int col = ntp * 16 + (lane >> 4) * 8;
                    ldsm_x4_t(bv[j], smaddr(Vt + buf * TSTRIDE + row * 72 + col));
                }
                #pragma unroll
                for (int j = 0; j < 2; j++) {
                    int ntp = g * 2 + j;
                    mma16816(o[2*ntp],   a, bv[j][0], bv[j][1]);
                    mma16816(o[2*ntp+1], a, bv[j][2], bv[j][3]);
                }
            }
            mma16816(o[8], a, ONESF, ONESF);
        }
    }

    float inv0 = 1.0f / o[8][0], inv1 = 1.0f / o[8][2];
    int r0 = q0 + warp * 16 + (lane >> 2);
    int r1 = r0 + 8;
    #pragma unroll
    for (int nt = 0; nt < 8; nt++) {
        int c = h * 64 + nt * 8 + 2 * (lane & 3);
        size_t i0 = ((size_t)b * S_ + r0) * (H_ * DV_) + c;
        size_t i1 = ((size_t)b * S_ + r1) * (H_ * DV_) + c;
        float2 q0v = *(const float2*)(qin + i0);
        float2 q1v = *(const float2*)(qin + i1);
        float2 o0, o1;
        o0.x = o[nt][0] * inv0 + q0v.x;
        o0.y = o[nt][1] * inv0 + q0v.y;
        o1.x = o[nt][2] * inv1 + q1v.x;
        o1.y = o[nt][3] * inv1 + q1v.y;
        *(float2*)(out + i0) = o0;
        *(float2*)(out + i1) = o1;
    }
}

extern "C" void kernel_launch(void* const* d_in, const int* in_sizes, int n_in,
                              void* d_out, int out_size)
{
    (void)in_sizes; (void)n_in; (void)out_size;
    const float* q    = (const float*)d_in[0];
    const float* k    = (const float*)d_in[1];
    const float* v    = (const float*)d_in[2];
    const int*   mask = (const int*)  d_in[3];
    const float* wq   = (const float*)d_in[4];
    const float* bq   = (const float*)d_in[5];
    const float* wk   = (const float*)d_in[6];
    const float* bk   = (const float*)d_in[7];
    const float* wv   = (const float*)d_in[8];
    const float* bv   = (const float*)d_in[9];
    float* out = (float*)d_out;

    static bool attr_set = false;
    if (!attr_set) {
        cudaFuncSetAttribute(proj_mma, cudaFuncAttributeMaxDynamicSharedMemorySize,
                             (int)sizeof(ProjSmem));
        attr_set = true;
    }

    int prep_blks = 3 * PREP_A_BLKS + 3 * PREP_W_BLKS + 1;
    prep<<<prep_blks, 256>>>(q, k, v, wq, wk, wv, mask);

    dim3 pg(DM / 128, ROWS / 128, 3);   // (8, 64, 3); z>0 early-exit past count
    proj_mma<<<pg, 256, sizeof(ProjSmem)>>>(bq, bk, bv);

    dim3 ag(S_ / 128, H_, B_);
    attn_mma<<<ag, 256, ATTN_SMEM>>>(q, out);
}